// round 11
// baseline (speedup 1.0000x reference)
#include <cuda_runtime.h>
#include <math_constants.h>

#define TPB    256
#define MC     4096                    // linear-interp cells
#define KMAX   1024
#define LOF    (-0.015625f)            // table domain start
#define HSTEP  (33.0f/131072.0f)       // cell width h (exact in fp32)
#define INVH   (131072.0f/33.0f)       // 1/h
#define TT0C   (2048.0f/33.0f - 0.5f)  // -LOF/h - 0.5 (cell-centered offset)
#define MAGICF 12582912.0f             // 1.5 * 2^23
#define BBLD   148                     // builder blocks

// Device scratch (no allocations allowed)
__device__ float4 g_params[KMAX];      // {mu, s=-0.5*inv_var*log2e, b=log2(coef), 0}
__device__ float2 g_coef[MC];          // per-cell linear {y_mid, dy}
__device__ int    g_interp;            // 1 -> interpolation valid
__device__ float  g_mx, g_tot;         // softmax stats (K>KMAX ultra-fallback)

__device__ __forceinline__ float ex2(float a) {
    float r;
    asm("ex2.approx.f32 %0, %1;" : "=f"(r) : "f"(a));
    return r;
}

__device__ __forceinline__ float wred_max(float v) {
#pragma unroll
    for (int o = 16; o; o >>= 1) v = fmaxf(v, __shfl_xor_sync(0xffffffffu, v, o));
    return v;
}
__device__ __forceinline__ float wred_min(float v) {
#pragma unroll
    for (int o = 16; o; o >>= 1) v = fminf(v, __shfl_xor_sync(0xffffffffu, v, o));
    return v;
}
__device__ __forceinline__ float wred_sum(float v) {
#pragma unroll
    for (int o = 16; o; o >>= 1) v += __shfl_xor_sync(0xffffffffu, v, o);
    return v;
}

// ---------------------------------------------------------------------------
// Builder: per-block softmax+params (warp shuffles), then one warp per cell
// (2-pt stencil at cell endpoints, lanes split K) -> {y_mid, dy} per cell.
// Signals dependent launch after all table writes complete.
// ---------------------------------------------------------------------------
__global__ __launch_bounds__(TPB)
void build_fused(const float* __restrict__ pi_l,
                 const float* __restrict__ mu,
                 const float* __restrict__ lv, int K) {
    __shared__ float4 sp[KMAX];        // 16 KB params
    __shared__ float  sred[8];
    int t   = threadIdx.x;
    int wid = t >> 5, lid = t & 31;
    int kok = (K <= KMAX);

    // ---- softmax max ----
    float m = -CUDART_INF_F;
    for (int k = t; k < K; k += TPB) m = fmaxf(m, pi_l[k]);
    m = wred_max(m);
    if (lid == 0) sred[wid] = m;
    __syncthreads();
    float mx = fmaxf(fmaxf(fmaxf(sred[0], sred[1]), fmaxf(sred[2], sred[3])),
                     fmaxf(fmaxf(sred[4], sred[5]), fmaxf(sred[6], sred[7])));
    __syncthreads();

    // ---- softmax sum ----
    float sum = 0.f;
    for (int k = t; k < K; k += TPB) sum += expf(pi_l[k] - mx);
    sum = wred_sum(sum);
    if (lid == 0) sred[wid] = sum;
    __syncthreads();
    float tot = sred[0] + sred[1] + sred[2] + sred[3]
              + sred[4] + sred[5] + sred[6] + sred[7];
    __syncthreads();

    // ---- params + min log-variance ----
    float lmin = CUDART_INF_F;
    if (kok) {
        for (int k = t; k < K; k += TPB) {
            float pi   = expf(pi_l[k] - mx) / tot;
            float l    = lv[k];
            lmin = fminf(lmin, l);
            float coef = pi * 0.39894228040143267794f * expf(-0.5f * l);
            float s2   = -0.5f * expf(-l) * 1.44269504088896340736f;
            float b    = log2f(fmaxf(coef, 1e-38f));
            sp[k] = make_float4(mu[k], s2, b, 0.f);
        }
    }
    lmin = wred_min(lmin);
    if (lid == 0) sred[wid] = lmin;
    __syncthreads();
    lmin = fminf(fminf(fminf(sred[0], sred[1]), fminf(sred[2], sred[3])),
                 fminf(fminf(sred[4], sred[5]), fminf(sred[6], sred[7])));

    if (blockIdx.x == 0) {
        if (kok) for (int k = t; k < K; k += TPB) g_params[k] = sp[k];
        if (t == 0) {
            // linear-interp err ~ |y''| h^2 / 8; require sigma >= 14h
            float smin = expf(0.5f * lmin);
            g_interp = (kok && smin >= 14.0f * HSTEP) ? 1 : 0;
            g_mx = mx; g_tot = tot;
        }
    }

    // ---- one warp per cell: endpoints stencil, lanes split K ----
    if (kok) {
        int warps_total = gridDim.x * (TPB >> 5);
        for (int cell = blockIdx.x * (TPB >> 5) + wid; cell < MC;
             cell += warps_total) {
            float x0 = LOF + (float)cell * HSTEP;
            float x1 = x0 + HSTEP;
            float a0 = 0.f, a1 = 0.f;
            for (int k = lid; k < K; k += 32) {
                float4 pp = sp[k];
                float d0 = x0 - pp.x;
                float d1 = x1 - pp.x;
                a0 += ex2(fmaf(d0 * d0, pp.y, pp.z));
                a1 += ex2(fmaf(d1 * d1, pp.y, pp.z));
            }
            a0 = wred_sum(a0);
            a1 = wred_sum(a1);
            if (lid == 0) {
                // p(f) = y_mid + f * dy, f in [-0.5, 0.5] around cell center
                float2 e;
                e.x = 0.5f * (a0 + a1);
                e.y = a1 - a0;
                g_coef[cell] = e;
            }
        }
    }

    // All table/flag writes done -> allow the dependent kernel to proceed.
    asm volatile("griddepcontrol.launch_dependents;");
}

// ---------------------------------------------------------------------------
// Cold fallbacks
// ---------------------------------------------------------------------------
__device__ __noinline__ float direct_eval(float x, int K) {
    float acc = 0.f;
    for (int k = 0; k < K; k++) {
        float4 p = g_params[k];
        float d = x - p.x;
        acc += ex2(fmaf(d * d, p.y, p.z));
    }
    return acc;
}

__device__ __noinline__ float direct_eval_raw(float x, const float* pi_l,
                                              const float* mu, const float* lv, int K) {
    float mx = g_mx, tot = g_tot;
    float acc = 0.f;
    for (int k = 0; k < K; k++) {
        float pi   = expf(pi_l[k] - mx) / tot;
        float l    = lv[k];
        float coef = pi * 0.39894228040143267794f * expf(-0.5f * l);
        float d    = x - mu[k];
        acc += coef * expf(-0.5f * d * d * expf(-l));
    }
    return acc;
}

// ---------------------------------------------------------------------------
// Hot eval: cell-centered linear, magic-number rounding (no F2I/I2F, no cvt).
// tt = x/h - LOF/h - 0.5; j = round(tt) in [0, MC-1]; f = tt - j in [-0.5,0.5].
// ---------------------------------------------------------------------------
__device__ __forceinline__ float interp1(float x, const float2* __restrict__ stab) {
    float tt = fmaf(x, INVH, TT0C);
    tt = fminf(fmaxf(tt, -0.5f), (float)MC - 1.0f);
    float tb = tt + MAGICF;
    unsigned int j = __float_as_uint(tb) & 0xFFFu;
    float f = tt - (tb - MAGICF);
    float2 e = stab[j];
    return fmaf(f, e.y, e.x);
}

__device__ __forceinline__ float4 interp4(float4 z, const float2* __restrict__ stab) {
    float4 r;
    r.x = interp1(z.x, stab);
    r.y = interp1(z.y, stab);
    r.z = interp1(z.z, stab);
    r.w = interp1(z.w, stab);
    return r;
}

__global__ __launch_bounds__(TPB, 6)
void interp_kernel(const float* __restrict__ mz,
                   float* __restrict__ out,
                   int n, int K,
                   const float* __restrict__ pi_l,
                   const float* __restrict__ mu,
                   const float* __restrict__ lv) {
    __shared__ float2 stab[MC];          // 32 KB

    int gtid = blockIdx.x * TPB + threadIdx.x;
    int gsz  = gridDim.x * TPB;
    int n4   = n >> 2;
    const float4* mz4 = (const float4*)mz;
    float4* out4 = (float4*)out;

    // --- Prologue (independent of builder): prefetch first MLP-4 batch ---
    float4 z0, z1, z2, z3;
    int i = gtid;
    bool pre = (i + 3 * gsz < n4);
    if (pre) {
        z0 = mz4[i];
        z1 = mz4[i + gsz];
        z2 = mz4[i + 2 * gsz];
        z3 = mz4[i + 3 * gsz];
    }

    // --- Wait for builder's results to be visible ---
    asm volatile("griddepcontrol.wait;" ::: "memory");

    int mode = g_interp;                 // uniform across grid
    if (mode) {
#pragma unroll 4
        for (int k = threadIdx.x; k < MC; k += TPB)
            stab[k] = g_coef[k];
        __syncthreads();

        if (pre) {
            out4[i]           = interp4(z0, stab);
            out4[i + gsz]     = interp4(z1, stab);
            out4[i + 2 * gsz] = interp4(z2, stab);
            out4[i + 3 * gsz] = interp4(z3, stab);
            i += 4 * gsz;
        }
        for (; i + 3 * gsz < n4; i += 4 * gsz) {
            float4 y0 = mz4[i];
            float4 y1 = mz4[i + gsz];
            float4 y2 = mz4[i + 2 * gsz];
            float4 y3 = mz4[i + 3 * gsz];
            out4[i]           = interp4(y0, stab);
            out4[i + gsz]     = interp4(y1, stab);
            out4[i + 2 * gsz] = interp4(y2, stab);
            out4[i + 3 * gsz] = interp4(y3, stab);
        }
        for (; i < n4; i += gsz) {
            out4[i] = interp4(mz4[i], stab);
        }
        int rem = n & 3;
        if (gtid < rem) {
            int j = (n4 << 2) + gtid;
            out[j] = interp1(mz[j], stab);
        }
    } else if (K <= KMAX) {
        for (int k = gtid; k < n; k += gsz)
            out[k] = direct_eval(mz[k], K);
    } else {
        for (int k = gtid; k < n; k += gsz)
            out[k] = direct_eval_raw(mz[k], pi_l, mu, lv, K);
    }
}

// ---------------------------------------------------------------------------
// Inputs (metadata order): mz [N], pi_l [K], mu [K], lv [K]. Output: prob [N] f32.
// ---------------------------------------------------------------------------
extern "C" void kernel_launch(void* const* d_in, const int* in_sizes, int n_in,
                              void* d_out, int out_size) {
    const float* mz   = (const float*)d_in[0];
    const float* pi_l = (const float*)d_in[1];
    const float* mu   = (const float*)d_in[2];
    const float* lv   = (const float*)d_in[3];
    float* out = (float*)d_out;
    int n = in_sizes[0];
    int K = in_sizes[1];

    build_fused<<<BBLD, TPB>>>(pi_l, mu, lv, K);

    int need = (n / 4 + TPB - 1) / TPB;
    if (need < 1) need = 1;
    int blocks = 148 * 6;                      // one resident wave at 6 CTA/SM
    if (blocks > need) blocks = need;

    // Programmatic dependent launch: interp starts early, overlapping the
    // builder; griddepcontrol.wait inside gates on the builder's writes.
    cudaLaunchConfig_t cfg = {};
    cfg.gridDim  = dim3((unsigned)blocks, 1, 1);
    cfg.blockDim = dim3(TPB, 1, 1);
    cfg.dynamicSmemBytes = 0;
    cfg.stream = 0;
    cudaLaunchAttribute attrs[1];
    attrs[0].id = cudaLaunchAttributeProgrammaticStreamSerialization;
    attrs[0].val.programmaticStreamSerializationAllowed = 1;
    cfg.attrs = attrs;
    cfg.numAttrs = 1;
    cudaLaunchKernelEx(&cfg, interp_kernel, mz, out, n, K, pi_l, mu, lv);
}

// round 12
// speedup vs baseline: 1.0173x; 1.0173x over previous
#include <cuda_runtime.h>
#include <cuda_fp16.h>
#include <math_constants.h>

#define TPB    1024
#define MI     2048                    // interpolation cells
#define YPTS   2050                    // y grid points (cells need y[i..i+2])
#define KWMAX  256                     // max K for windowed build
#define W      12                      // window width (components per node)
#define LOF    (-0.015625f)            // table domain start
#define HSTEP  (33.0f/65536.0f)        // cell width h (exact in fp32)
#define INVH   (65536.0f/33.0f)        // 1/h
#define TT0    (1024.0f/33.0f)         // -LOF/h

__device__ __forceinline__ float ex2(float a) {
    float r;
    asm("ex2.approx.f32 %0, %1;" : "=f"(r) : "f"(a));
    return r;
}

__device__ __forceinline__ float wred_max(float v) {
#pragma unroll
    for (int o = 16; o; o >>= 1) v = fmaxf(v, __shfl_xor_sync(0xffffffffu, v, o));
    return v;
}
__device__ __forceinline__ float wred_min(float v) {
#pragma unroll
    for (int o = 16; o; o >>= 1) v = fminf(v, __shfl_xor_sync(0xffffffffu, v, o));
    return v;
}
__device__ __forceinline__ float wred_sum(float v) {
#pragma unroll
    for (int o = 16; o; o >>= 1) v += __shfl_xor_sync(0xffffffffu, v, o);
    return v;
}

// ---------------------------------------------------------------------------
// Hot eval (R7-proven): cell quadratic, one LDS.64 + half2 cvt + 2-FMA Horner.
// ---------------------------------------------------------------------------
__device__ __forceinline__ float interp1(float x, const float2* __restrict__ stab) {
    float t = fmaf(x, INVH, TT0);
    int i = __float2int_rz(t);
    i = min(max(i, 0), MI - 1);
    float f = t - (float)i;
    float2 e = stab[i];
    unsigned int u = __float_as_uint(e.y);
    __half2 h12 = *reinterpret_cast<__half2*>(&u);
    float2 c = __half22float2(h12);
    return fmaf(f, fmaf(f, c.y, c.x), e.x);
}

__device__ __forceinline__ float4 interp4(float4 z, const float2* __restrict__ stab) {
    float4 r;
    r.x = interp1(z.x, stab);
    r.y = interp1(z.y, stab);
    r.z = interp1(z.z, stab);
    r.w = interp1(z.w, stab);
    return r;
}

// ---------------------------------------------------------------------------
// Single kernel, one CTA per SM. Each block redundantly:
//   softmax + params (K <= 256) + structure checks,
//   WINDOWED table build (24 ex2/thread) into its own smem,
//   then streams its share of points through the table.
// Any check failure -> exact direct evaluation fallback (slow, correct).
// ---------------------------------------------------------------------------
__global__ __launch_bounds__(TPB, 1)
void gmm_one(const float* __restrict__ mz,
             float* __restrict__ out,
             int n, int K,
             const float* __restrict__ pi_l,
             const float* __restrict__ mu,
             const float* __restrict__ lv) {
    __shared__ float4 sp[KWMAX];          // 4 KB   params {mu, s, b, 0}
    __shared__ float  sy[YPTS + 2];       // 8.2 KB raw table y values
    __shared__ float2 stab[MI];           // 16 KB  packed quadratic coefs
    __shared__ float  sred[64];

    int t   = threadIdx.x;
    int wid = t >> 5, lid = t & 31;
    int nwarp = TPB >> 5;

    // ---- softmax max ----
    float m = -CUDART_INF_F;
    for (int k = t; k < K; k += TPB) m = fmaxf(m, pi_l[k]);
    m = wred_max(m);
    if (lid == 0) sred[wid] = m;
    __syncthreads();
    if (wid == 0) {
        float v = (lid < nwarp) ? sred[lid] : -CUDART_INF_F;
        v = wred_max(v);
        if (lid == 0) sred[0] = v;
    }
    __syncthreads();
    float mx = sred[0];
    __syncthreads();

    // ---- softmax sum ----
    float sum = 0.f;
    for (int k = t; k < K; k += TPB) sum += expf(pi_l[k] - mx);
    sum = wred_sum(sum);
    if (lid == 0) sred[wid] = sum;
    __syncthreads();
    if (wid == 0) {
        float v = (lid < nwarp) ? sred[lid] : 0.f;
        v = wred_sum(v);
        if (lid == 0) sred[0] = v;
    }
    __syncthreads();
    float tot = sred[0];
    __syncthreads();

    // ---- params + structure checks ----
    int kok = (K >= W && K <= KWMAX);
    float dK = 1.0f / (float)(K - 1);
    float lmin = CUDART_INF_F, lmax = -CUDART_INF_F;
    int okm = 1;
    if (kok) {
        for (int k = t; k < K; k += TPB) {
            float l   = lv[k];
            float muk = mu[k];
            lmin = fminf(lmin, l);
            lmax = fmaxf(lmax, l);
            float pi   = expf(pi_l[k] - mx) / tot;
            float coef = pi * 0.39894228040143267794f * expf(-0.5f * l);
            float s2   = -0.5f * expf(-l) * 1.44269504088896340736f;
            float b    = log2f(fmaxf(coef, 1e-38f));
            sp[k] = make_float4(muk, s2, b, 0.f);
            if (!(fabsf(muk - (float)k * dK) <= 1.2f * dK)) okm = 0;
        }
    }
    lmin = wred_min(lmin);
    lmax = wred_max(lmax);
    if (lid == 0) { sred[wid] = lmin; sred[32 + wid] = lmax; }
    int ok_all = __syncthreads_and(okm && kok);
    if (wid == 0) {
        float a = (lid < nwarp) ? sred[lid] : CUDART_INF_F;
        float b = (lid < nwarp) ? sred[32 + lid] : -CUDART_INF_F;
        a = wred_min(a);
        b = wred_max(b);
        if (lid == 0) { sred[0] = a; sred[1] = b; }
    }
    __syncthreads();
    float smin = expf(0.5f * sred[0]);
    float smax = expf(0.5f * sred[1]);
    // quadratic accuracy needs sigma >= 5.5h; window truncation needs
    // sigma <= 0.65*spacing given mu within 1.2*spacing of linspace.
    int mode = ok_all && (smin >= 5.5f * HSTEP) && (smax <= 0.65f * dK);
    __syncthreads();

    // ---- windowed table build: y at YPTS grid points, W terms each ----
    if (mode) {
        float scaleK = (float)(K - 1);
        int kcl = K - W;
        for (int g = t; g < YPTS; g += TPB) {
            float x = LOF + (float)g * HSTEP;
            int kc = __float2int_rn(x * scaleK);
            int k0 = min(max(kc - 5, 0), kcl);
            const float4* q = sp + k0;
            float a0 = 0.f, a1 = 0.f;
#pragma unroll
            for (int j = 0; j < W; j += 2) {
                float4 p0 = q[j];
                float4 p1 = q[j + 1];
                float d0 = x - p0.x;
                float d1 = x - p1.x;
                a0 += ex2(fmaf(d0 * d0, p0.y, p0.z));
                a1 += ex2(fmaf(d1 * d1, p1.y, p1.z));
            }
            sy[g] = a0 + a1;
        }
    }
    __syncthreads();
    if (mode) {
        for (int i = t; i < MI; i += TPB) {
            float y0 = sy[i], y1 = sy[i + 1], y2 = sy[i + 2];
            float c1 = fmaf(-1.5f, y0, fmaf(2.0f, y1, -0.5f * y2));
            float c2 = fmaf(0.5f, y0, fmaf(-1.0f, y1, 0.5f * y2));
            __half2 h12 = __floats2half2_rn(c1, c2);
            float2 e;
            e.x = y0;
            e.y = __uint_as_float(*reinterpret_cast<unsigned int*>(&h12));
            stab[i] = e;
        }
    }
    __syncthreads();

    // ---- main stream ----
    int gtid = blockIdx.x * TPB + t;
    int gsz  = gridDim.x * TPB;
    int n4   = n >> 2;
    const float4* mz4 = (const float4*)mz;
    float4* out4 = (float4*)out;

    if (mode) {
        int i = gtid;
        for (; i + 3 * gsz < n4; i += 4 * gsz) {
            float4 z0 = mz4[i];
            float4 z1 = mz4[i + gsz];
            float4 z2 = mz4[i + 2 * gsz];
            float4 z3 = mz4[i + 3 * gsz];
            out4[i]           = interp4(z0, stab);
            out4[i + gsz]     = interp4(z1, stab);
            out4[i + 2 * gsz] = interp4(z2, stab);
            out4[i + 3 * gsz] = interp4(z3, stab);
        }
        for (; i < n4; i += gsz) {
            out4[i] = interp4(mz4[i], stab);
        }
        int rem = n & 3;
        if (gtid < rem) {
            int j = (n4 << 2) + gtid;
            out[j] = interp1(mz[j], stab);
        }
    } else {
        // exact direct fallback (any K, any structure) using block's mx/tot
        for (int i = gtid; i < n; i += gsz) {
            float x = mz[i];
            float acc = 0.f;
            for (int k = 0; k < K; k++) {
                float pi   = expf(pi_l[k] - mx) / tot;
                float l    = lv[k];
                float coef = pi * 0.39894228040143267794f * expf(-0.5f * l);
                float d    = x - mu[k];
                acc += coef * expf(-0.5f * d * d * expf(-l));
            }
            out[i] = acc;
        }
    }
}

// ---------------------------------------------------------------------------
// Inputs (metadata order): mz [N], pi_l [K], mu [K], lv [K]. Output: prob [N] f32.
// ---------------------------------------------------------------------------
extern "C" void kernel_launch(void* const* d_in, const int* in_sizes, int n_in,
                              void* d_out, int out_size) {
    const float* mz   = (const float*)d_in[0];
    const float* pi_l = (const float*)d_in[1];
    const float* mu   = (const float*)d_in[2];
    const float* lv   = (const float*)d_in[3];
    float* out = (float*)d_out;
    int n = in_sizes[0];
    int K = in_sizes[1];

    int need = (n / 4 + TPB - 1) / TPB;
    if (need < 1) need = 1;
    int blocks = 148;                 // one CTA per SM, single wave
    if (blocks > need) blocks = need;
    gmm_one<<<blocks, TPB>>>(mz, out, n, K, pi_l, mu, lv);
}